// round 15
// baseline (speedup 1.0000x reference)
#include <cuda_runtime.h>
#include <cuda_bf16.h>
#include <mma.h>
#include <math.h>

using namespace nvcuda;

#define N_NODES  100000
#define N_EDGES  1600000
#define NH       128
#define N_GRAPHS 512
#define N_CLASS  10
#define SCAN_B   1024
#define SCAN_G   98

// -------- scratch (device globals; no allocation allowed) --------
__device__ __nv_bfloat16 g_h1[N_NODES * NH];  // dinv-prescaled x@W1 (bf16)
__device__ __nv_bfloat16 g_h2[N_NODES * NH];  // dinv-prescaled BN/ReLU out (bf16)
__device__ __nv_bfloat16 g_W1h[NH * NH];      // W1 in bf16
__device__ float g_bnA[NH];                   // gamma / sqrt(1+eps)
__device__ float g_bnB[NH];                   // b1*bnA + beta
__device__ float g_dinv[N_NODES];
__device__ int   g_deg[N_NODES];              // 1 + in-degree
__device__ int   g_rowStart[N_NODES];
__device__ int   g_cursor[N_NODES];
__device__ int   g_esrc[N_EDGES];             // edge sources grouped by dst
__device__ float g_sums[N_GRAPHS * NH];
// lookback-scan state
__device__ int   g_blkAgg[SCAN_G];
__device__ int   g_blkPref[SCAN_G];
__device__ volatile int g_blkFlag[SCAN_G];    // 0=pending 1=agg 2=prefix

// ================= setup =================
__global__ void k_init0() {
    int i = blockIdx.x * blockDim.x + threadIdx.x;
    if (i < N_NODES) g_deg[i] = 1;
    if (i < N_GRAPHS * NH) g_sums[i] = 0.f;
    if (i < SCAN_G) g_blkFlag[i] = 0;
}

__global__ void k_count(const int* __restrict__ dst) {
    int e = blockIdx.x * blockDim.x + threadIdx.x;
    if (e < N_EDGES) atomicAdd(&g_deg[dst[e]], 1);
}

__global__ void k_dinv() {
    int i = blockIdx.x * blockDim.x + threadIdx.x;
    if (i < N_NODES) g_dinv[i] = rsqrtf((float)g_deg[i]);
}

// ---- single-kernel decoupled-lookback exclusive scan of (deg-1) ----
// 98 blocks <= SM count: all resident, spin-wait is safe.
__global__ void k_scan() {
    __shared__ int s[SCAN_B];
    __shared__ int sPrev;
    int t = threadIdx.x, b = blockIdx.x;
    int i = b * SCAN_B + t;
    int v = (i < N_NODES) ? (g_deg[i] - 1) : 0;
    s[t] = v;
    __syncthreads();
    for (int off = 1; off < SCAN_B; off <<= 1) {
        int add = (t >= off) ? s[t - off] : 0;
        __syncthreads();
        s[t] += add;
        __syncthreads();
    }
    int incl = s[t];
    if (t == 0) {
        int total = s[SCAN_B - 1];
        g_blkAgg[b] = total;
        __threadfence();
        g_blkFlag[b] = 1;
        int prev = 0;
        for (int j = b - 1; j >= 0; ) {
            int f;
            do { f = g_blkFlag[j]; } while (f == 0);
            __threadfence();
            if (f == 2) { prev += g_blkPref[j]; break; }
            prev += g_blkAgg[j];
            j--;
        }
        g_blkPref[b] = prev + total;
        __threadfence();
        g_blkFlag[b] = 2;
        sPrev = prev;
    }
    __syncthreads();
    if (i < N_NODES) {
        int rs = sPrev + incl - v;   // exclusive
        g_rowStart[i] = rs;
        g_cursor[i]   = rs;
    }
}

__global__ void k_fill(const int* __restrict__ srcp, const int* __restrict__ dstp) {
    int e = blockIdx.x * blockDim.x + threadIdx.x;
    if (e < N_EDGES) {
        int s = srcp[e], d = dstp[e];
        int pos = atomicAdd(&g_cursor[d], 1);
        g_esrc[pos] = s;
    }
}

// ============ W1 fp32 -> bf16, plus BN constant prep ============
__global__ void k_wconv(const float* __restrict__ W, const float* __restrict__ b1,
                        const float* __restrict__ gamma, const float* __restrict__ beta) {
    int i = blockIdx.x * blockDim.x + threadIdx.x;
    if (i < NH * NH) g_W1h[i] = __float2bfloat16_rn(W[i]);
    if (i < NH) {
        float a = gamma[i] * rsqrtf(1.0f + 1e-5f);
        g_bnA[i] = a;
        g_bnB[i] = b1[i] * a + beta[i];
    }
}

// ==== GEMM1 (bf16 tensor cores, 256 thr): g_h1 = dinv * (bf16(x) @ bf16(W1)) ====
// 8 warps: warp w -> rows [ (w>>1)*16 , +16 ), cols [ (w&1)*64 , +64 )
__global__ void k_gemmT(const float* __restrict__ A) {
    __shared__ __align__(16) char smemraw[49152];
    __nv_bfloat16* sA = (__nv_bfloat16*)smemraw;             // 64 x 128
    __nv_bfloat16* sW = (__nv_bfloat16*)(smemraw + 16384);   // 128 x 128
    float*         sC = (float*)smemraw;                     // epilogue reuse
    int t = threadIdx.x;
    int w = t >> 5;
    int wr = w >> 1, wc = w & 1;
    long row0 = (long)blockIdx.x * 64;

    const int4* Wh4 = (const int4*)g_W1h;
    int4* sW4 = (int4*)sW;
    for (int i = t; i < 2048; i += 256) sW4[i] = Wh4[i];

    const float4* A4 = (const float4*)A;
    __nv_bfloat162* sA2 = (__nv_bfloat162*)sA;
    for (int i = t; i < 2048; i += 256) {
        int r = i >> 5, c = i & 31;
        long rg = row0 + r; if (rg >= N_NODES) rg = N_NODES - 1;
        float4 v = A4[rg * 32 + c];
        sA2[r * 64 + c * 2]     = __floats2bfloat162_rn(v.x, v.y);
        sA2[r * 64 + c * 2 + 1] = __floats2bfloat162_rn(v.z, v.w);
    }
    __syncthreads();

    wmma::fragment<wmma::accumulator, 16, 16, 16, float> cf[4];
#pragma unroll
    for (int n = 0; n < 4; n++) wmma::fill_fragment(cf[n], 0.f);
#pragma unroll
    for (int k0 = 0; k0 < 8; k0++) {
        wmma::fragment<wmma::matrix_a, 16, 16, 16, __nv_bfloat16, wmma::row_major> af;
        wmma::load_matrix_sync(af, sA + (wr * 16) * 128 + k0 * 16, 128);
#pragma unroll
        for (int n = 0; n < 4; n++) {
            wmma::fragment<wmma::matrix_b, 16, 16, 16, __nv_bfloat16, wmma::row_major> bf;
            wmma::load_matrix_sync(bf, sW + (k0 * 16) * 128 + wc * 64 + n * 16, 128);
            wmma::mma_sync(cf[n], af, bf, cf[n]);
        }
    }
    __syncthreads();
#pragma unroll
    for (int n = 0; n < 4; n++)
        wmma::store_matrix_sync(sC + (wr * 16) * 128 + wc * 64 + n * 16, cf[n], 128,
                                wmma::mem_row_major);
    __syncthreads();

    __nv_bfloat162* out2 = (__nv_bfloat162*)g_h1;
    const float2* sC2 = (const float2*)sC;
    for (int i = t; i < 64 * 64; i += 256) {
        int r = i >> 6, c = i & 63;
        long rg = row0 + r;
        if (rg < N_NODES) {
            float dv = g_dinv[rg];
            float2 v = sC2[r * 64 + c];
            out2[rg * 64 + c] = __floats2bfloat162_rn(v.x * dv, v.y * dv);
        }
    }
}

// -------- gather helpers: bf16 expansion via bit ops (alu pipe, no F2F) --------
__device__ __forceinline__ void accb8(float* acc, int4 raw) {
    unsigned* u = (unsigned*)&raw;
#pragma unroll
    for (int k = 0; k < 4; k++) {
        acc[2 * k]     += __int_as_float(u[k] << 16);
        acc[2 * k + 1] += __int_as_float(u[k] & 0xFFFF0000u);
    }
}

// One node per WARP; two convergent half-warps alternate edges (same trip count).
__device__ __forceinline__ void gather_node(const int4* in4, int d, int half, int li,
                                            float* acc) {
    int start = g_rowStart[d];
    int len   = g_deg[d] - 1;
    if (half == 0) {
        int4 raw = in4[(long)d * 16 + li];
        unsigned* u = (unsigned*)&raw;
#pragma unroll
        for (int k = 0; k < 4; k++) {
            acc[2 * k]     = __int_as_float(u[k] << 16);
            acc[2 * k + 1] = __int_as_float(u[k] & 0xFFFF0000u);
        }
    } else {
#pragma unroll
        for (int k = 0; k < 8; k++) acc[k] = 0.f;
    }
    const int* ep = g_esrc + start;
    int j = half;
    for (; j + 6 < len; j += 8) {
        int s0 = ep[j],     s1 = ep[j + 2];
        int s2 = ep[j + 4], s3 = ep[j + 6];
        int4 r0 = in4[(long)s0 * 16 + li];
        int4 r1 = in4[(long)s1 * 16 + li];
        int4 r2 = in4[(long)s2 * 16 + li];
        int4 r3 = in4[(long)s3 * 16 + li];
        accb8(acc, r0);
        accb8(acc, r1);
        accb8(acc, r2);
        accb8(acc, r3);
    }
    for (; j < len; j += 2) {
        int4 r = in4[(long)ep[j] * 16 + li];
        accb8(acc, r);
    }
#pragma unroll
    for (int k = 0; k < 8; k++)
        acc[k] += __shfl_down_sync(0xffffffffu, acc[k], 16);
}

// ======= gather layer 1: agg -> *dinv -> BN(+b1) -> ReLU -> *dinv -> g_h2 =======
__global__ void __launch_bounds__(256, 4)
k_gather1() {
    int d = blockIdx.x * 8 + (threadIdx.x >> 5);
    int lane = threadIdx.x & 31;
    int half = lane >> 4, li = lane & 15;
    if (d >= N_NODES) return;
    float acc[8];
    gather_node((const int4*)g_h1, d, half, li, acc);
    if (half == 0) {
        float dv = g_dinv[d];
        int c8 = li * 8;
        float4 A0 = *(const float4*)&g_bnA[c8], A1 = *(const float4*)&g_bnA[c8 + 4];
        float4 B0 = *(const float4*)&g_bnB[c8], B1 = *(const float4*)&g_bnB[c8 + 4];
        float Aa[8] = {A0.x, A0.y, A0.z, A0.w, A1.x, A1.y, A1.z, A1.w};
        float Bb[8] = {B0.x, B0.y, B0.z, B0.w, B1.x, B1.y, B1.z, B1.w};
        __nv_bfloat162 o[4];
#pragma unroll
        for (int k = 0; k < 4; k++) {
            float v0 = fmaxf((acc[2 * k]     * dv) * Aa[2 * k]     + Bb[2 * k],     0.f) * dv;
            float v1 = fmaxf((acc[2 * k + 1] * dv) * Aa[2 * k + 1] + Bb[2 * k + 1], 0.f) * dv;
            o[k] = __floats2bfloat162_rn(v0, v1);
        }
        ((int4*)g_h2)[(long)d * 16 + li] = *(int4*)o;
    }
}

// ===== gather layer 2: agg -> *dinv -> pool into g_sums via smem staging =====
__global__ void __launch_bounds__(256, 4)
k_gather2(const int* __restrict__ batch) {
    __shared__ float sbuf[4][NH];
    __shared__ int sbase;
    int t = threadIdx.x;
    int w = t >> 5, lane = t & 31;
    int half = lane >> 4, li = lane & 15;
    int nb = blockIdx.x * 32;
    if (t == 0) sbase = batch[nb < N_NODES ? nb : N_NODES - 1];
    for (int i = t; i < 4 * NH; i += 256) ((float*)sbuf)[i] = 0.f;
    __syncthreads();
    int base = sbase;
    const int4* in4 = (const int4*)g_h2;

    for (int i = 0; i < 4; i++) {
        int d = nb + w * 4 + i;
        if (d >= N_NODES) break;
        float acc[8];
        gather_node(in4, d, half, li, acc);
        if (half == 0) {
            float dv = g_dinv[d];
            int b = batch[d];
            int slot = b - base;
            int c8 = li * 8;
            if (slot >= 0 && slot < 4) {
#pragma unroll
                for (int k = 0; k < 8; k++) atomicAdd(&sbuf[slot][c8 + k], acc[k] * dv);
            } else {
#pragma unroll
                for (int k = 0; k < 8; k++) atomicAdd(&g_sums[b * NH + c8 + k], acc[k] * dv);
            }
        }
    }
    __syncthreads();
    for (int i = t; i < 4 * NH; i += 256) {
        float v = ((float*)sbuf)[i];
        int slot = i >> 7, c = i & 127;
        int b = base + slot;
        if (v != 0.f && b < N_GRAPHS) atomicAdd(&g_sums[b * NH + c], v);
    }
}

// ==== final: cnt via binary search on sorted batch; tiny GEMM + log_softmax ====
__global__ void k_final(const int* __restrict__ batch,
                        const float* __restrict__ W2, const float* __restrict__ b2,
                        const float* __restrict__ clsW, const float* __restrict__ clsb,
                        float* __restrict__ out) {
    int gph = blockIdx.x;
    int t = threadIdx.x;
    __shared__ float sp[NH];
    __shared__ float sg[NH];
    __shared__ float sl[N_CLASS];
    __shared__ float lse;
    __shared__ int scnt;
    if (t == 0) {
        int lo = 0, hi = N_NODES;
        while (lo < hi) { int m = (lo + hi) >> 1; if (batch[m] < gph) lo = m + 1; else hi = m; }
        int l0 = lo;
        lo = l0; hi = N_NODES;
        while (lo < hi) { int m = (lo + hi) >> 1; if (batch[m] < gph + 1) lo = m + 1; else hi = m; }
        scnt = lo - l0;
    }
    sp[t] = g_sums[gph * NH + t];
    __syncthreads();
    float cnt = fmaxf((float)scnt, 1.0f);
    float acc = 0.f;
#pragma unroll 8
    for (int k = 0; k < NH; k++) acc += sp[k] * W2[k * NH + t];
    float gv = acc / cnt + b2[t];
    sg[t] = gv;
    out[N_GRAPHS * N_CLASS + gph * NH + t] = gv;
    __syncthreads();
    if (t < N_CLASS) {
        float a2 = clsb[t];
        for (int k = 0; k < NH; k++) a2 += sg[k] * clsW[k * N_CLASS + t];
        sl[t] = a2;
    }
    __syncthreads();
    if (t == 0) {
        float m = sl[0];
        for (int i = 1; i < N_CLASS; i++) m = fmaxf(m, sl[i]);
        float s = 0.f;
        for (int i = 0; i < N_CLASS; i++) s += expf(sl[i] - m);
        lse = m + logf(s);
    }
    __syncthreads();
    if (t < N_CLASS) out[gph * N_CLASS + t] = sl[t] - lse;
}

extern "C" void kernel_launch(void* const* d_in, const int* in_sizes, int n_in,
                              void* d_out, int out_size) {
    const float* x     = (const float*)d_in[0];
    const int*   ei    = (const int*)d_in[1];
    const int*   batch = (const int*)d_in[2];
    const float* W1    = (const float*)d_in[3];
    const float* b1    = (const float*)d_in[4];
    const float* gamma = (const float*)d_in[5];
    const float* beta  = (const float*)d_in[6];
    const float* W2    = (const float*)d_in[7];
    const float* b2    = (const float*)d_in[8];
    const float* clsW  = (const float*)d_in[9];
    const float* clsb  = (const float*)d_in[10];
    float* out = (float*)d_out;

    const int* srcp = ei;
    const int* dstp = ei + N_EDGES;

    const int TPB = 256;
    int nodeBlocks = (N_NODES + TPB - 1) / TPB;
    int edgeBlocks = (N_EDGES + TPB - 1) / TPB;

    static cudaStream_t s1 = []() {
        cudaStream_t s; cudaStreamCreateWithFlags(&s, cudaStreamNonBlocking); return s;
    }();
    static cudaEvent_t evCnt = []() {
        cudaEvent_t e; cudaEventCreateWithFlags(&e, cudaEventDisableTiming); return e;
    }();
    static cudaEvent_t evFill = []() {
        cudaEvent_t e; cudaEventCreateWithFlags(&e, cudaEventDisableTiming); return e;
    }();

    // main: deg counting (both branches need deg)
    k_init0<<<nodeBlocks, TPB>>>();
    k_count<<<edgeBlocks, TPB>>>(dstp);
    cudaEventRecord(evCnt, 0);

    // s1: CSR build (fused lookback scan + metadata fill) — needs only deg
    cudaStreamWaitEvent(s1, evCnt, 0);
    k_scan<<<SCAN_G, SCAN_B, 0, s1>>>();
    k_fill<<<edgeBlocks, TPB, 0, s1>>>(srcp, dstp);
    cudaEventRecord(evFill, s1);

    // main: dinv, wconv, bf16 tensor-core GEMM with dinv-prescaled epilogue
    k_dinv<<<nodeBlocks, TPB>>>();
    k_wconv<<<64, 256>>>(W1, b1, gamma, beta);
    k_gemmT<<<(N_NODES + 63) / 64, 256>>>(x);

    // join, then gathers + final
    cudaStreamWaitEvent(0, evFill, 0);
    k_gather1<<<(N_NODES + 7) / 8, 256>>>();
    k_gather2<<<(N_NODES + 31) / 32, 256>>>(batch);
    k_final<<<N_GRAPHS, NH>>>(batch, W2, b2, clsW, clsb, out);
}

// round 16
// speedup vs baseline: 1.4531x; 1.4531x over previous
#include <cuda_runtime.h>
#include <cuda_bf16.h>
#include <mma.h>
#include <math.h>

using namespace nvcuda;

#define N_NODES  100000
#define N_EDGES  1600000
#define NH       128
#define N_GRAPHS 512
#define N_CLASS  10
#define SCAN_B   1024
#define SCAN_G   98

// -------- scratch (device globals; no allocation allowed) --------
__device__ __nv_bfloat16 g_h1[N_NODES * NH];  // dinv-prescaled x@W1 (bf16)
__device__ __nv_bfloat16 g_h2[N_NODES * NH];  // dinv-prescaled BN/ReLU out (bf16)
__device__ float g_bnA[NH];                   // gamma / sqrt(1+eps)
__device__ float g_bnB[NH];                   // b1*bnA + beta
__device__ float g_dinv[N_NODES];
__device__ int   g_deg[N_NODES];              // 1 + in-degree
__device__ int   g_rowStart[N_NODES];
__device__ int   g_cursor[N_NODES];
__device__ int   g_esrc[N_EDGES];             // edge sources grouped by dst
__device__ int   g_bsum[128];
__device__ int   g_boff[128];
__device__ float g_sums[N_GRAPHS * NH];

// ================= setup =================
__global__ void k_init0() {
    int i = blockIdx.x * blockDim.x + threadIdx.x;
    if (i < N_NODES) g_deg[i] = 1;
    if (i < N_GRAPHS * NH) g_sums[i] = 0.f;
}

__global__ void k_count(const int* __restrict__ dst) {
    int e = blockIdx.x * blockDim.x + threadIdx.x;
    if (e < N_EDGES) atomicAdd(&g_deg[dst[e]], 1);
}

// dinv per node + BN constants (threads < NH of block 0)
__global__ void k_dinv(const float* __restrict__ b1, const float* __restrict__ gamma,
                       const float* __restrict__ beta) {
    int i = blockIdx.x * blockDim.x + threadIdx.x;
    if (i < N_NODES) g_dinv[i] = rsqrtf((float)g_deg[i]);
    if (i < NH) {
        float a = gamma[i] * rsqrtf(1.0f + 1e-5f);
        g_bnA[i] = a;
        g_bnB[i] = b1[i] * a + beta[i];
    }
}

__global__ void k_scanA() {
    __shared__ int s[SCAN_B];
    int t = threadIdx.x;
    int i = blockIdx.x * SCAN_B + t;
    int v = (i < N_NODES) ? (g_deg[i] - 1) : 0;
    s[t] = v;
    __syncthreads();
    for (int off = 1; off < SCAN_B; off <<= 1) {
        int add = (t >= off) ? s[t - off] : 0;
        __syncthreads();
        s[t] += add;
        __syncthreads();
    }
    if (i < N_NODES) g_rowStart[i] = s[t] - v;
    if (t == SCAN_B - 1) g_bsum[blockIdx.x] = s[t];
}

__global__ void k_scanB() {
    __shared__ int s[128];
    int t = threadIdx.x;
    int v = (t < SCAN_G) ? g_bsum[t] : 0;
    s[t] = v;
    __syncthreads();
    for (int off = 1; off < 128; off <<= 1) {
        int add = (t >= off) ? s[t - off] : 0;
        __syncthreads();
        s[t] += add;
        __syncthreads();
    }
    if (t < SCAN_G) g_boff[t] = s[t] - v;   // exclusive
}

__global__ void k_scanC() {
    int i = blockIdx.x * SCAN_B + threadIdx.x;
    if (i < N_NODES) {
        int rs = g_rowStart[i] + g_boff[blockIdx.x];
        g_rowStart[i] = rs;
        g_cursor[i]   = rs;
    }
}

__global__ void k_fill(const int* __restrict__ srcp, const int* __restrict__ dstp) {
    int e = blockIdx.x * blockDim.x + threadIdx.x;
    if (e < N_EDGES) {
        int s = srcp[e], d = dstp[e];
        int pos = atomicAdd(&g_cursor[d], 1);
        g_esrc[pos] = s;
    }
}

// ==== GEMM1 (bf16 tensor cores, 256 thr): g_h1 = dinv * (bf16(x) @ bf16(W1)) ====
// W converted fp32->bf16 during smem staging (no separate wconv kernel).
// 8 warps: warp w -> rows [ (w>>1)*16, +16 ), cols [ (w&1)*64, +64 )
__global__ void k_gemmT(const float* __restrict__ A, const float* __restrict__ W) {
    __shared__ __align__(16) char smemraw[49152];
    __nv_bfloat16* sA = (__nv_bfloat16*)smemraw;             // 64 x 128
    __nv_bfloat16* sW = (__nv_bfloat16*)(smemraw + 16384);   // 128 x 128
    float*         sC = (float*)smemraw;                     // epilogue reuse
    int t = threadIdx.x;
    int w = t >> 5;
    int wr = w >> 1, wc = w & 1;
    long row0 = (long)blockIdx.x * 64;

    // stage W with on-the-fly conversion: 128x128 fp32 -> bf16
    const float4* W4 = (const float4*)W;
    __nv_bfloat162* sW2 = (__nv_bfloat162*)sW;
    for (int i = t; i < 4096; i += 256) {
        float4 v = W4[i];
        sW2[i * 2]     = __floats2bfloat162_rn(v.x, v.y);
        sW2[i * 2 + 1] = __floats2bfloat162_rn(v.z, v.w);
    }

    const float4* A4 = (const float4*)A;
    __nv_bfloat162* sA2 = (__nv_bfloat162*)sA;
    for (int i = t; i < 2048; i += 256) {
        int r = i >> 5, c = i & 31;
        long rg = row0 + r; if (rg >= N_NODES) rg = N_NODES - 1;
        float4 v = A4[rg * 32 + c];
        sA2[r * 64 + c * 2]     = __floats2bfloat162_rn(v.x, v.y);
        sA2[r * 64 + c * 2 + 1] = __floats2bfloat162_rn(v.z, v.w);
    }
    __syncthreads();

    wmma::fragment<wmma::accumulator, 16, 16, 16, float> cf[4];
#pragma unroll
    for (int n = 0; n < 4; n++) wmma::fill_fragment(cf[n], 0.f);
#pragma unroll
    for (int k0 = 0; k0 < 8; k0++) {
        wmma::fragment<wmma::matrix_a, 16, 16, 16, __nv_bfloat16, wmma::row_major> af;
        wmma::load_matrix_sync(af, sA + (wr * 16) * 128 + k0 * 16, 128);
#pragma unroll
        for (int n = 0; n < 4; n++) {
            wmma::fragment<wmma::matrix_b, 16, 16, 16, __nv_bfloat16, wmma::row_major> bf;
            wmma::load_matrix_sync(bf, sW + (k0 * 16) * 128 + wc * 64 + n * 16, 128);
            wmma::mma_sync(cf[n], af, bf, cf[n]);
        }
    }
    __syncthreads();
#pragma unroll
    for (int n = 0; n < 4; n++)
        wmma::store_matrix_sync(sC + (wr * 16) * 128 + wc * 64 + n * 16, cf[n], 128,
                                wmma::mem_row_major);
    __syncthreads();

    __nv_bfloat162* out2 = (__nv_bfloat162*)g_h1;
    const float2* sC2 = (const float2*)sC;
    for (int i = t; i < 64 * 64; i += 256) {
        int r = i >> 6, c = i & 63;
        long rg = row0 + r;
        if (rg < N_NODES) {
            float dv = g_dinv[rg];
            float2 v = sC2[r * 64 + c];
            out2[rg * 64 + c] = __floats2bfloat162_rn(v.x * dv, v.y * dv);
        }
    }
}

// -------- gather helpers: bf16 expansion via bit ops (alu pipe, no F2F) --------
__device__ __forceinline__ void accb8(float* acc, int4 raw) {
    unsigned* u = (unsigned*)&raw;
#pragma unroll
    for (int k = 0; k < 4; k++) {
        acc[2 * k]     += __int_as_float(u[k] << 16);
        acc[2 * k + 1] += __int_as_float(u[k] & 0xFFFF0000u);
    }
}

// One node per WARP; two convergent half-warps alternate edges (same trip count).
__device__ __forceinline__ void gather_node(const int4* in4, int d, int half, int li,
                                            float* acc) {
    int start = g_rowStart[d];
    int len   = g_deg[d] - 1;
    if (half == 0) {
        int4 raw = in4[(long)d * 16 + li];
        unsigned* u = (unsigned*)&raw;
#pragma unroll
        for (int k = 0; k < 4; k++) {
            acc[2 * k]     = __int_as_float(u[k] << 16);
            acc[2 * k + 1] = __int_as_float(u[k] & 0xFFFF0000u);
        }
    } else {
#pragma unroll
        for (int k = 0; k < 8; k++) acc[k] = 0.f;
    }
    const int* ep = g_esrc + start;
    int j = half;
    for (; j + 6 < len; j += 8) {
        int s0 = ep[j],     s1 = ep[j + 2];
        int s2 = ep[j + 4], s3 = ep[j + 6];
        int4 r0 = in4[(long)s0 * 16 + li];
        int4 r1 = in4[(long)s1 * 16 + li];
        int4 r2 = in4[(long)s2 * 16 + li];
        int4 r3 = in4[(long)s3 * 16 + li];
        accb8(acc, r0);
        accb8(acc, r1);
        accb8(acc, r2);
        accb8(acc, r3);
    }
    for (; j < len; j += 2) {
        int4 r = in4[(long)ep[j] * 16 + li];
        accb8(acc, r);
    }
#pragma unroll
    for (int k = 0; k < 8; k++)
        acc[k] += __shfl_down_sync(0xffffffffu, acc[k], 16);
}

// ======= gather layer 1: agg -> *dinv -> BN(+b1) -> ReLU -> *dinv -> g_h2 =======
__global__ void __launch_bounds__(256, 4)
k_gather1() {
    int d = blockIdx.x * 8 + (threadIdx.x >> 5);
    int lane = threadIdx.x & 31;
    int half = lane >> 4, li = lane & 15;
    if (d >= N_NODES) return;
    float acc[8];
    gather_node((const int4*)g_h1, d, half, li, acc);
    if (half == 0) {
        float dv = g_dinv[d];
        int c8 = li * 8;
        float4 A0 = *(const float4*)&g_bnA[c8], A1 = *(const float4*)&g_bnA[c8 + 4];
        float4 B0 = *(const float4*)&g_bnB[c8], B1 = *(const float4*)&g_bnB[c8 + 4];
        float Aa[8] = {A0.x, A0.y, A0.z, A0.w, A1.x, A1.y, A1.z, A1.w};
        float Bb[8] = {B0.x, B0.y, B0.z, B0.w, B1.x, B1.y, B1.z, B1.w};
        __nv_bfloat162 o[4];
#pragma unroll
        for (int k = 0; k < 4; k++) {
            float v0 = fmaxf((acc[2 * k]     * dv) * Aa[2 * k]     + Bb[2 * k],     0.f) * dv;
            float v1 = fmaxf((acc[2 * k + 1] * dv) * Aa[2 * k + 1] + Bb[2 * k + 1], 0.f) * dv;
            o[k] = __floats2bfloat162_rn(v0, v1);
        }
        ((int4*)g_h2)[(long)d * 16 + li] = *(int4*)o;
    }
}

// ===== gather layer 2: agg -> *dinv -> pool into g_sums via smem staging =====
__global__ void __launch_bounds__(256, 4)
k_gather2(const int* __restrict__ batch) {
    __shared__ float sbuf[4][NH];
    __shared__ int sbase;
    int t = threadIdx.x;
    int w = t >> 5, lane = t & 31;
    int half = lane >> 4, li = lane & 15;
    int nb = blockIdx.x * 32;
    if (t == 0) sbase = batch[nb < N_NODES ? nb : N_NODES - 1];
    for (int i = t; i < 4 * NH; i += 256) ((float*)sbuf)[i] = 0.f;
    __syncthreads();
    int base = sbase;
    const int4* in4 = (const int4*)g_h2;

    for (int i = 0; i < 4; i++) {
        int d = nb + w * 4 + i;
        if (d >= N_NODES) break;
        float acc[8];
        gather_node(in4, d, half, li, acc);
        if (half == 0) {
            float dv = g_dinv[d];
            int b = batch[d];
            int slot = b - base;
            int c8 = li * 8;
            if (slot >= 0 && slot < 4) {
#pragma unroll
                for (int k = 0; k < 8; k++) atomicAdd(&sbuf[slot][c8 + k], acc[k] * dv);
            } else {
#pragma unroll
                for (int k = 0; k < 8; k++) atomicAdd(&g_sums[b * NH + c8 + k], acc[k] * dv);
            }
        }
    }
    __syncthreads();
    for (int i = t; i < 4 * NH; i += 256) {
        float v = ((float*)sbuf)[i];
        int slot = i >> 7, c = i & 127;
        int b = base + slot;
        if (v != 0.f && b < N_GRAPHS) atomicAdd(&g_sums[b * NH + c], v);
    }
}

// ==== final: cnt via binary search on sorted batch; tiny GEMM + log_softmax ====
__global__ void k_final(const int* __restrict__ batch,
                        const float* __restrict__ W2, const float* __restrict__ b2,
                        const float* __restrict__ clsW, const float* __restrict__ clsb,
                        float* __restrict__ out) {
    int gph = blockIdx.x;
    int t = threadIdx.x;
    __shared__ float sp[NH];
    __shared__ float sg[NH];
    __shared__ float sl[N_CLASS];
    __shared__ float lse;
    __shared__ int scnt;
    if (t == 0) {
        int lo = 0, hi = N_NODES;
        while (lo < hi) { int m = (lo + hi) >> 1; if (batch[m] < gph) lo = m + 1; else hi = m; }
        int l0 = lo;
        lo = l0; hi = N_NODES;
        while (lo < hi) { int m = (lo + hi) >> 1; if (batch[m] < gph + 1) lo = m + 1; else hi = m; }
        scnt = lo - l0;
    }
    sp[t] = g_sums[gph * NH + t];
    __syncthreads();
    float cnt = fmaxf((float)scnt, 1.0f);
    float acc = 0.f;
#pragma unroll 8
    for (int k = 0; k < NH; k++) acc += sp[k] * W2[k * NH + t];
    float gv = acc / cnt + b2[t];
    sg[t] = gv;
    out[N_GRAPHS * N_CLASS + gph * NH + t] = gv;
    __syncthreads();
    if (t < N_CLASS) {
        float a2 = clsb[t];
        for (int k = 0; k < NH; k++) a2 += sg[k] * clsW[k * N_CLASS + t];
        sl[t] = a2;
    }
    __syncthreads();
    if (t == 0) {
        float m = sl[0];
        for (int i = 1; i < N_CLASS; i++) m = fmaxf(m, sl[i]);
        float s = 0.f;
        for (int i = 0; i < N_CLASS; i++) s += expf(sl[i] - m);
        lse = m + logf(s);
    }
    __syncthreads();
    if (t < N_CLASS) out[gph * N_CLASS + t] = sl[t] - lse;
}

extern "C" void kernel_launch(void* const* d_in, const int* in_sizes, int n_in,
                              void* d_out, int out_size) {
    const float* x     = (const float*)d_in[0];
    const int*   ei    = (const int*)d_in[1];
    const int*   batch = (const int*)d_in[2];
    const float* W1    = (const float*)d_in[3];
    const float* b1    = (const float*)d_in[4];
    const float* gamma = (const float*)d_in[5];
    const float* beta  = (const float*)d_in[6];
    const float* W2    = (const float*)d_in[7];
    const float* b2    = (const float*)d_in[8];
    const float* clsW  = (const float*)d_in[9];
    const float* clsb  = (const float*)d_in[10];
    float* out = (float*)d_out;

    const int* srcp = ei;
    const int* dstp = ei + N_EDGES;

    const int TPB = 256;
    int nodeBlocks = (N_NODES + TPB - 1) / TPB;
    int edgeBlocks = (N_EDGES + TPB - 1) / TPB;

    static cudaStream_t s1 = []() {
        cudaStream_t s; cudaStreamCreateWithFlags(&s, cudaStreamNonBlocking); return s;
    }();
    static cudaEvent_t evDeg = []() {
        cudaEvent_t e; cudaEventCreateWithFlags(&e, cudaEventDisableTiming); return e;
    }();
    static cudaEvent_t evFill = []() {
        cudaEvent_t e; cudaEventCreateWithFlags(&e, cudaEventDisableTiming); return e;
    }();

    // main: degree counting (both branches need deg)
    k_init0<<<nodeBlocks, TPB>>>();
    k_count<<<edgeBlocks, TPB>>>(dstp);
    cudaEventRecord(evDeg, 0);

    // s1: CSR build (3-launch scan + metadata fill) — needs only deg
    cudaStreamWaitEvent(s1, evDeg, 0);
    k_scanA<<<SCAN_G, SCAN_B, 0, s1>>>();
    k_scanB<<<1, 128, 0, s1>>>();
    k_scanC<<<SCAN_G, SCAN_B, 0, s1>>>();
    k_fill<<<edgeBlocks, TPB, 0, s1>>>(srcp, dstp);
    cudaEventRecord(evFill, s1);

    // main: dinv+BN consts, then bf16 tensor-core GEMM (W converted in-kernel)
    k_dinv<<<nodeBlocks, TPB>>>(b1, gamma, beta);
    k_gemmT<<<(N_NODES + 63) / 64, 256>>>(x, W1);

    // join, then gathers + final
    cudaStreamWaitEvent(0, evFill, 0);
    k_gather1<<<(N_NODES + 7) / 8, 256>>>();
    k_gather2<<<(N_NODES + 31) / 32, 256>>>(batch);
    k_final<<<N_GRAPHS, NH>>>(batch, W2, b2, clsW, clsb, out);
}